// round 10
// baseline (speedup 1.0000x reference)
#include <cuda_runtime.h>
#include <cuda_fp16.h>

#define NN      131072
#define KK      27
#define C       32
#define NKTOT   (NN * KK)
#define DCAP    64                 // bucket width (Poisson(27): P(any overflow) ~ 7e-5)
#define EPS_F   1e-5f
#define GB      8192               // gather blocks = BN partial count
#define MIDB    256

// -------- device scratch --------
__device__ __align__(16) __half g_sorted[((size_t)NN * DCAP + 1) * C]; // 537 MB bucketed rows
__device__ int    g_fill[NN];
__device__ int    g_dposT[(size_t)KK * NN];                 // 13.5 MB: slot per (k, n)
__device__ float  g_part[GB * 64];
__device__ float  g_part2[MIDB * 64];
__device__ float  g_stats[64];
__device__ __align__(16) unsigned g_bfrag[108 * 2 * 32 * 2]; // 55 KB: B in mma frag order

__device__ __forceinline__ unsigned smem_u32(const void* p) {
    unsigned a;
    asm("{ .reg .u64 t; cvta.to.shared.u64 t, %1; cvt.u32.u64 %0, t; }" : "=r"(a) : "l"(p));
    return a;
}

// -------- 1. init: zero fill counters + pre-swizzle B into mma frag order ----
// Bfrag[nt][s][lane][reg]: k0 = s*16 + (l&3)*2 + reg*8, n = nt*8 + (l>>2),
// value half2( B[k0][n], B[k0+1][n] ), B[i][j] = weight[j/32][i][j%32].
__global__ void k_init(const float* __restrict__ weight) {
    int i = blockIdx.x * blockDim.x + threadIdx.x;
    if (i < NN) g_fill[i] = 0;
    if (i < 108 * 2 * 32 * 2) {
        int reg = i & 1, l = (i >> 1) & 31, s = (i >> 6) & 1, nt = i >> 7;
        int k0 = s * 16 + (l & 3) * 2 + reg * 8;
        int n  = nt * 8 + (l >> 2);
        int jk = n >> 5, o = n & 31;
        float lo = weight[(jk * 32 + k0) * 32 + o];
        float hi = weight[(jk * 32 + k0 + 1) * 32 + o];
        __half2 h = __floats2half2_rn(lo, hi);
        g_bfrag[i] = *reinterpret_cast<unsigned*>(&h);
    }
}

// -------- 2. fill: count buckets + record destination slot per (k, n) -------
__global__ __launch_bounds__(256) void k_fill(const int* __restrict__ neigh) {
    __shared__ int sn[256 * KK];
    int base = blockIdx.x * 256;
    for (int i = threadIdx.x; i < 256 * KK; i += 256)
        sn[i] = neigh[(size_t)base * KK + i];
    __syncthreads();
    int n = base + threadIdx.x;
#pragma unroll
    for (int j = 0; j < KK; ++j) {
        int m   = sn[threadIdx.x * KK + j];
        int pos = atomicAdd(&g_fill[m], 1);
        int slot = (pos < DCAP) ? (m * DCAP + pos) : (NN * DCAP);  // overflow row
        g_dposT[(size_t)j * NN + n] = slot;                         // coalesced in n
    }
}

// -------- 3. GEMM: row (n,k) -> g_sorted[slot(n,k)] (64B scatter) -----------
// CTA = 128 rows; A-frags in regs (ldmatrix once); B-frags from L1-hot table.
// Column perm within row: p = j*8 + t*2 + b <-> channel o = t*8 + j*2 + b.
__global__ __launch_bounds__(256) void k_gemm(const float* __restrict__ data) {
    __shared__ __align__(16) __half Ah[128][40];
    const int tid = threadIdx.x, lane = tid & 31, warp = tid >> 5;
    const int bid = blockIdx.x;

    const float4* src = reinterpret_cast<const float4*>(data + (size_t)bid * 128 * C);
#pragma unroll
    for (int t0 = 0; t0 < 4; ++t0) {
        int    t = tid + t0 * 256;
        float4 v = src[t];
        int r = t >> 3, c = (t & 7) * 4;
        *reinterpret_cast<__half2*>(&Ah[r][c])     = __floats2half2_rn(v.x, v.y);
        *reinterpret_cast<__half2*>(&Ah[r][c + 2]) = __floats2half2_rn(v.z, v.w);
    }
    __syncthreads();

    unsigned a0[4], a1[4];
    {
        unsigned base = smem_u32(&Ah[warp * 16 + (lane & 15)][(lane >> 4) * 8]);
        asm volatile("ldmatrix.sync.aligned.m8n8.x4.shared.b16 {%0,%1,%2,%3}, [%4];"
                     : "=r"(a0[0]), "=r"(a0[1]), "=r"(a0[2]), "=r"(a0[3]) : "r"(base));
        asm volatile("ldmatrix.sync.aligned.m8n8.x4.shared.b16 {%0,%1,%2,%3}, [%4];"
                     : "=r"(a1[0]), "=r"(a1[1]), "=r"(a1[2]), "=r"(a1[3]) : "r"(base + 32));
    }

    const int r0 = lane >> 2;
    const int j  = lane & 3;
    const int nbase = bid * 128 + warp * 16;
    const uint2* bf = reinterpret_cast<const uint2*>(g_bfrag) + lane;

    for (int kb = 0; kb < 27; ++kb) {
        int dp  = g_dposT[(size_t)kb * NN + nbase + (lane & 15)];
        int dlo = __shfl_sync(0xffffffffu, dp, r0);
        int dhi = __shfl_sync(0xffffffffu, dp, r0 + 8);

        uint2 b[8];
#pragma unroll
        for (int q = 0; q < 8; ++q) b[q] = bf[(kb * 8 + q) * 32];

        unsigned hlo[4], hhi[4];
#pragma unroll
        for (int t = 0; t < 4; ++t) {
            float d0 = 0.f, d1 = 0.f, d2 = 0.f, d3 = 0.f;
            asm volatile(
                "mma.sync.aligned.m16n8k16.row.col.f32.f16.f16.f32 "
                "{%0,%1,%2,%3}, {%4,%5,%6,%7}, {%8,%9}, {%0,%1,%2,%3};"
                : "+f"(d0), "+f"(d1), "+f"(d2), "+f"(d3)
                : "r"(a0[0]), "r"(a0[1]), "r"(a0[2]), "r"(a0[3]),
                  "r"(b[t * 2].x), "r"(b[t * 2].y));
            asm volatile(
                "mma.sync.aligned.m16n8k16.row.col.f32.f16.f16.f32 "
                "{%0,%1,%2,%3}, {%4,%5,%6,%7}, {%8,%9}, {%0,%1,%2,%3};"
                : "+f"(d0), "+f"(d1), "+f"(d2), "+f"(d3)
                : "r"(a1[0]), "r"(a1[1]), "r"(a1[2]), "r"(a1[3]),
                  "r"(b[t * 2 + 1].x), "r"(b[t * 2 + 1].y));
            __half2 l2 = __floats2half2_rn(d0, d1);
            __half2 h2 = __floats2half2_rn(d2, d3);
            hlo[t] = *reinterpret_cast<unsigned*>(&l2);
            hhi[t] = *reinterpret_cast<unsigned*>(&h2);
        }
        uint4 vlo = make_uint4(hlo[0], hlo[1], hlo[2], hlo[3]);
        uint4 vhi = make_uint4(hhi[0], hhi[1], hhi[2], hhi[3]);
        __stcs(reinterpret_cast<uint4*>(g_sorted + (size_t)dlo * C + j * 8), vlo);
        __stcs(reinterpret_cast<uint4*>(g_sorted + (size_t)dhi * C + j * 8), vhi);
    }
}

// -------- 4. gather + BN stage-1: sequential bucket reads, no index list ----
// warp = node m; bucket rows are contiguous at g_sorted[m*DCAP ...].
// lane: g = lane>>3 row-in-block, c = lane&7 reads 8B (4 channels);
// 8 rows per iter via 2 independent LDG.64; tail predicated (garbage skipped).
__global__ __launch_bounds__(512) void k_gather(float* __restrict__ out) {
    __shared__ float sm[16][33];
    const int tid = threadIdx.x, lane = tid & 31, w = tid >> 5;
    const int m = blockIdx.x * 16 + w;
    const int g = lane >> 3, c = lane & 7;

    int cnt = g_fill[m];
    if (cnt > DCAP) cnt = DCAP;
    const __half* base = g_sorted + (size_t)m * DCAP * C;

    float4 acc = make_float4(0.f, 0.f, 0.f, 0.f);
    for (int j = 0; j < cnt; j += 8) {
        uint2 d1 = __ldcs(reinterpret_cast<const uint2*>(base + (j + g)     * C) + c);
        uint2 d2 = __ldcs(reinterpret_cast<const uint2*>(base + (j + 4 + g) * C) + c);
        if (j + g < cnt) {
            float2 f;
            f = __half22float2(*reinterpret_cast<__half2*>(&d1.x)); acc.x += f.x; acc.y += f.y;
            f = __half22float2(*reinterpret_cast<__half2*>(&d1.y)); acc.z += f.x; acc.w += f.y;
        }
        if (j + 4 + g < cnt) {
            float2 f;
            f = __half22float2(*reinterpret_cast<__half2*>(&d2.x)); acc.x += f.x; acc.y += f.y;
            f = __half22float2(*reinterpret_cast<__half2*>(&d2.y)); acc.z += f.x; acc.w += f.y;
        }
    }
    acc.x += __shfl_down_sync(0xffffffffu, acc.x, 8);
    acc.y += __shfl_down_sync(0xffffffffu, acc.y, 8);
    acc.z += __shfl_down_sync(0xffffffffu, acc.z, 8);
    acc.w += __shfl_down_sync(0xffffffffu, acc.w, 8);
    acc.x += __shfl_down_sync(0xffffffffu, acc.x, 16);
    acc.y += __shfl_down_sync(0xffffffffu, acc.y, 16);
    acc.z += __shfl_down_sync(0xffffffffu, acc.z, 16);
    acc.w += __shfl_down_sync(0xffffffffu, acc.w, 16);

    if (lane < 8) {
        // undo column permutation: half2 idx p2 -> channel (p2&3)*8 + (p2>>2)*2
        int co0 = ((2 * c)     & 3) * 8 + ((2 * c)     >> 2) * 2;
        int co1 = ((2 * c + 1) & 3) * 8 + ((2 * c + 1) >> 2) * 2;
        *reinterpret_cast<float2*>(out + (size_t)m * C + co0) = make_float2(acc.x, acc.y);
        *reinterpret_cast<float2*>(out + (size_t)m * C + co1) = make_float2(acc.z, acc.w);
        sm[w][co0] = acc.x; sm[w][co0 + 1] = acc.y;
        sm[w][co1] = acc.z; sm[w][co1 + 1] = acc.w;
    }
    __syncthreads();
    if (tid < 32) {                      // deterministic per-CTA BN partials
        float s = 0.f, q = 0.f;
#pragma unroll
        for (int r = 0; r < 16; ++r) {
            float v = sm[r][tid];
            s += v; q += v * v;
        }
        g_part[blockIdx.x * 64 + tid]      = s;
        g_part[blockIdx.x * 64 + 32 + tid] = q;
    }
}

// -------- 5. BN partial reduction: 8192 -> 256 --------
__global__ __launch_bounds__(256) void k_bnmid() {
    __shared__ float ss[8][32], sq[8][32];
    int ch = threadIdx.x & 31, w = threadIdx.x >> 5;
    float s = 0.f, q = 0.f;
    for (int p = blockIdx.x * 32 + w; p < (blockIdx.x + 1) * 32; p += 8) {
        s += g_part[p * 64 + ch];
        q += g_part[p * 64 + 32 + ch];
    }
    ss[w][ch] = s; sq[w][ch] = q;
    __syncthreads();
    if (w == 0) {
        float S = 0.f, Q = 0.f;
#pragma unroll
        for (int t = 0; t < 8; ++t) { S += ss[t][ch]; Q += sq[t][ch]; }
        g_part2[blockIdx.x * 64 + ch]      = S;
        g_part2[blockIdx.x * 64 + 32 + ch] = Q;
    }
}

// -------- 6. BN finalize --------
__global__ __launch_bounds__(256) void k_bnfinal(const float* __restrict__ gamma,
                                                 const float* __restrict__ beta) {
    __shared__ float ss[8][32], sq[8][32];
    int ch = threadIdx.x & 31, w = threadIdx.x >> 5;
    float S = 0.f, Q = 0.f;
    for (int b = w; b < MIDB; b += 8) {
        S += g_part2[b * 64 + ch];
        Q += g_part2[b * 64 + 32 + ch];
    }
    ss[w][ch] = S; sq[w][ch] = Q;
    __syncthreads();
    if (w == 0) {
        float St = 0.f, Qt = 0.f;
#pragma unroll
        for (int t = 0; t < 8; ++t) { St += ss[t][ch]; Qt += sq[t][ch]; }
        float mean  = St * (1.0f / NN);
        float var   = Qt * (1.0f / NN) - mean * mean;
        float rstd  = rsqrtf(var + EPS_F);
        float scale = gamma[ch] * rstd;
        g_stats[ch]      = scale;
        g_stats[32 + ch] = beta[ch] - mean * scale;
    }
}

// -------- 7. apply BN + ReLU --------
__global__ __launch_bounds__(256) void k_apply(float* __restrict__ out) {
    int i = blockIdx.x * blockDim.x + threadIdx.x;
    if (i >= NN * C) return;
    int   ch = i & 31;
    float y  = fmaf(out[i], g_stats[ch], g_stats[32 + ch]);
    out[i] = fmaxf(y, 0.f);
}

extern "C" void kernel_launch(void* const* d_in, const int* in_sizes, int n_in,
                              void* d_out, int out_size) {
    const float* data   = (const float*)d_in[0];
    const float* weight = (const float*)d_in[1];
    const float* gamma  = (const float*)d_in[2];
    const float* beta   = (const float*)d_in[3];
    const int*   neigh  = (const int*)d_in[4];
    float*       out    = (float*)d_out;

    k_init<<<NN / 256, 256>>>(weight);
    k_fill<<<NN / 256, 256>>>(neigh);
    k_gemm<<<NN / 128, 256>>>(data);
    k_gather<<<GB, 512>>>(out);
    k_bnmid<<<MIDB, 256>>>();
    k_bnfinal<<<1, 256>>>(gamma, beta);
    k_apply<<<(NN * C + 255) / 256, 256>>>(out);
}